// round 5
// baseline (speedup 1.0000x reference)
#include <cuda_runtime.h>
#include <cuda_fp16.h>
#include <cstdint>

#define SEQ   2048
#define NH    32
#define NKV   8
#define HD    128
#define BM    64
#define BN    64
#define QSTRIDE  (NH*HD)
#define KVSTRIDE (NKV*HD)
// scale * log2(e): softmax done in base-2 domain
#define QSCALE (0.08838834764831845f * 1.4426950408889634f)

#define SSTRIDE 136                     /* fp16 elems per smem row (128 + 8 pad) */
#define QS_OFF 0
#define KS_OFF (BM * SSTRIDE * 2)
#define VS_OFF (KS_OFF + BN * SSTRIDE * 2)
#define SMEM_BYTES (VS_OFF + BN * SSTRIDE * 2)   /* 52224 */

__device__ __forceinline__ uint32_t smem_u32(const void* p) {
    uint32_t a;
    asm("{ .reg .u64 t; cvta.to.shared.u64 t, %1; cvt.u32.u64 %0, t; }" : "=r"(a) : "l"(p));
    return a;
}

#define LDSM_X4(r0,r1,r2,r3,a) \
    asm volatile("ldmatrix.sync.aligned.m8n8.x4.shared.b16 {%0,%1,%2,%3}, [%4];" \
                 : "=r"(r0),"=r"(r1),"=r"(r2),"=r"(r3) : "r"(a))
#define LDSM_X4T(r0,r1,r2,r3,a) \
    asm volatile("ldmatrix.sync.aligned.m8n8.x4.trans.shared.b16 {%0,%1,%2,%3}, [%4];" \
                 : "=r"(r0),"=r"(r1),"=r"(r2),"=r"(r3) : "r"(a))

#define MMA16816(d, a, b0, b1) \
    asm volatile("mma.sync.aligned.m16n8k16.row.col.f32.f16.f16.f32 " \
                 "{%0,%1,%2,%3}, {%4,%5,%6,%7}, {%8,%9}, {%0,%1,%2,%3};" \
                 : "+f"((d)[0]),"+f"((d)[1]),"+f"((d)[2]),"+f"((d)[3]) \
                 : "r"((a)[0]),"r"((a)[1]),"r"((a)[2]),"r"((a)[3]),"r"(b0),"r"(b1))

__device__ __forceinline__ float ex2f(float x) {
    float r;
    asm("ex2.approx.ftz.f32 %0, %1;" : "=f"(r) : "f"(x));
    return r;
}
__device__ __forceinline__ uint32_t packh2(float a, float b) {
    __half2 h = __floats2half2_rn(a, b);
    return *(uint32_t*)&h;
}

__global__ __launch_bounds__(128, 2)
void attn_hmma_kernel(const float* __restrict__ q, const float* __restrict__ k,
                      const float* __restrict__ v, float* __restrict__ out)
{
    extern __shared__ char smem[];
    const uint32_t sb = smem_u32(smem);
    const int tid  = threadIdx.x;
    const int wid  = tid >> 5;
    const int lane = tid & 31;
    const int qt   = 31 - (int)blockIdx.x;        // long CTAs first
    const int h    = (int)blockIdx.y;
    const int hk   = h >> 2;
    const int q0   = qt * BM;
    const int NT   = qt + 1;                      // KV tiles of 64

    // per-thread slot within a 64x128 fp32 tile (16 float4 slots)
    const int ldr  = tid >> 5;                    // rows 0..3 (+4 per it)
    const int ldc4 = (tid & 31) << 2;             // float4 col

    // ---- load Q (scaled, fp16) into SMEM ----
    {
        const float* qb = q + (size_t)q0 * QSTRIDE + (size_t)h * HD;
        #pragma unroll
        for (int it = 0; it < 16; ++it) {
            int r = it * 4 + ldr;
            float4 val = *(const float4*)(qb + (size_t)r * QSTRIDE + ldc4);
            uint2 hh;
            hh.x = packh2(val.x * QSCALE, val.y * QSCALE);
            hh.y = packh2(val.z * QSCALE, val.w * QSCALE);
            *(uint2*)(smem + QS_OFF + (r * SSTRIDE + ldc4) * 2) = hh;
        }
    }
    __syncthreads();

    // ---- Q A-fragments into registers (held for the whole kernel) ----
    uint32_t qa[8][4];
    {
        int row = wid * 16 + (lane & 15);
        #pragma unroll
        for (int ks = 0; ks < 8; ++ks) {
            uint32_t a = sb + QS_OFF + (row * SSTRIDE + ks * 16 + (lane >> 4) * 8) * 2;
            LDSM_X4(qa[ks][0], qa[ks][1], qa[ks][2], qa[ks][3], a);
        }
    }

    float oacc[16][4];
    #pragma unroll
    for (int i = 0; i < 16; ++i)
        #pragma unroll
        for (int j = 0; j < 4; ++j) oacc[i][j] = 0.f;
    float m0 = -1e30f, m1 = -1e30f, l0 = 0.f, l1 = 0.f;

    const int rr0 = q0 + wid * 16 + (lane >> 2);
    const float* kb_head = k + (size_t)hk * HD + (size_t)ldr * KVSTRIDE + ldc4;
    const float* vb_head = v + (size_t)hk * HD + (size_t)ldr * KVSTRIDE + ldc4;

    float4 kreg[16], vreg[16];

    // ---- prologue: prefetch K tile 0 ----
    #pragma unroll
    for (int it = 0; it < 16; ++it)
        kreg[it] = *(const float4*)(kb_head + (size_t)it * 4 * KVSTRIDE);

    for (int jt = 0; jt < NT; ++jt) {
        const int j0 = jt * BN;

        // ---- commit K(jt) regs -> fp16 smem; prefetch V(jt) ----
        #pragma unroll
        for (int it = 0; it < 16; ++it) {
            uint2 hh;
            hh.x = packh2(kreg[it].x, kreg[it].y);
            hh.y = packh2(kreg[it].z, kreg[it].w);
            *(uint2*)(smem + KS_OFF + ((ldr + it * 4) * SSTRIDE + ldc4) * 2) = hh;
        }
        #pragma unroll
        for (int it = 0; it < 16; ++it)
            vreg[it] = *(const float4*)(vb_head + (size_t)(j0 + it * 4) * KVSTRIDE);
        __syncthreads();

        // ---- S = Q @ K^T  (8 n-tiles x 4 k-steps x 2) ----
        float sacc[8][4];
        #pragma unroll
        for (int i = 0; i < 8; ++i)
            #pragma unroll
            for (int j = 0; j < 4; ++j) sacc[i][j] = 0.f;

        #pragma unroll
        for (int nt = 0; nt < 8; ++nt) {
            uint32_t krow = sb + KS_OFF + ((nt * 8 + (lane & 7)) * SSTRIDE) * 2;
            #pragma unroll
            for (int kp = 0; kp < 4; ++kp) {
                uint32_t b0, b1, b2, b3;
                uint32_t a = krow + (kp * 32 + (lane >> 3) * 8) * 2;
                LDSM_X4(b0, b1, b2, b3, a);
                MMA16816(sacc[nt], qa[2 * kp],     b0, b1);
                MMA16816(sacc[nt], qa[2 * kp + 1], b2, b3);
            }
        }

        // ---- causal mask (only the diagonal tile) ----
        if (jt == NT - 1) {
            #pragma unroll
            for (int nt = 0; nt < 8; ++nt) {
                int jc = j0 + nt * 8 + ((lane & 3) << 1);
                if (jc     > rr0    ) sacc[nt][0] = -1e30f;
                if (jc + 1 > rr0    ) sacc[nt][1] = -1e30f;
                if (jc     > rr0 + 8) sacc[nt][2] = -1e30f;
                if (jc + 1 > rr0 + 8) sacc[nt][3] = -1e30f;
            }
        }

        // ---- online softmax (rows rr0, rr0+8; stats shared in quad) ----
        float mx0 = -1e30f, mx1 = -1e30f;
        #pragma unroll
        for (int nt = 0; nt < 8; ++nt) {
            mx0 = fmaxf(mx0, fmaxf(sacc[nt][0], sacc[nt][1]));
            mx1 = fmaxf(mx1, fmaxf(sacc[nt][2], sacc[nt][3]));
        }
        mx0 = fmaxf(mx0, __shfl_xor_sync(0xffffffffu, mx0, 1));
        mx0 = fmaxf(mx0, __shfl_xor_sync(0xffffffffu, mx0, 2));
        mx1 = fmaxf(mx1, __shfl_xor_sync(0xffffffffu, mx1, 1));
        mx1 = fmaxf(mx1, __shfl_xor_sync(0xffffffffu, mx1, 2));

        float mn0 = fmaxf(m0, mx0), mn1 = fmaxf(m1, mx1);
        float al0 = ex2f(m0 - mn0), al1 = ex2f(m1 - mn1);
        m0 = mn0; m1 = mn1;

        float sum0 = 0.f, sum1 = 0.f;
        #pragma unroll
        for (int nt = 0; nt < 8; ++nt) {
            sacc[nt][0] = ex2f(sacc[nt][0] - mn0);
            sacc[nt][1] = ex2f(sacc[nt][1] - mn0);
            sacc[nt][2] = ex2f(sacc[nt][2] - mn1);
            sacc[nt][3] = ex2f(sacc[nt][3] - mn1);
            sum0 += sacc[nt][0] + sacc[nt][1];
            sum1 += sacc[nt][2] + sacc[nt][3];
        }
        sum0 += __shfl_xor_sync(0xffffffffu, sum0, 1);
        sum0 += __shfl_xor_sync(0xffffffffu, sum0, 2);
        sum1 += __shfl_xor_sync(0xffffffffu, sum1, 1);
        sum1 += __shfl_xor_sync(0xffffffffu, sum1, 2);
        l0 = l0 * al0 + sum0;
        l1 = l1 * al1 + sum1;

        // ---- pack P into A-fragments (no SMEM round-trip) ----
        uint32_t pa[4][4];
        #pragma unroll
        for (int t = 0; t < 4; ++t) {
            pa[t][0] = packh2(sacc[2 * t][0],     sacc[2 * t][1]);
            pa[t][1] = packh2(sacc[2 * t][2],     sacc[2 * t][3]);
            pa[t][2] = packh2(sacc[2 * t + 1][0], sacc[2 * t + 1][1]);
            pa[t][3] = packh2(sacc[2 * t + 1][2], sacc[2 * t + 1][3]);
        }

        // ---- commit V(jt) regs -> fp16 smem; prefetch K(jt+1) ----
        #pragma unroll
        for (int it = 0; it < 16; ++it) {
            uint2 hh;
            hh.x = packh2(vreg[it].x, vreg[it].y);
            hh.y = packh2(vreg[it].z, vreg[it].w);
            *(uint2*)(smem + VS_OFF + ((ldr + it * 4) * SSTRIDE + ldc4) * 2) = hh;
        }
        if (jt + 1 < NT) {
            #pragma unroll
            for (int it = 0; it < 16; ++it)
                kreg[it] = *(const float4*)(kb_head + (size_t)(j0 + BN + it * 4) * KVSTRIDE);
        }
        __syncthreads();

        // ---- rescale O ----
        #pragma unroll
        for (int nt = 0; nt < 16; ++nt) {
            oacc[nt][0] *= al0; oacc[nt][1] *= al0;
            oacc[nt][2] *= al1; oacc[nt][3] *= al1;
        }

        // ---- O += P @ V  (8 d-pairs x 4 k-steps; V via ldmatrix.trans) ----
        #pragma unroll
        for (int dp = 0; dp < 8; ++dp) {
            #pragma unroll
            for (int kt = 0; kt < 4; ++kt) {
                uint32_t b0, b1, b2, b3;
                uint32_t a = sb + VS_OFF +
                    (((kt * 16) + (lane & 15)) * SSTRIDE + dp * 16 + (lane >> 4) * 8) * 2;
                LDSM_X4T(b0, b1, b2, b3, a);
                MMA16816(oacc[2 * dp],     pa[kt], b0, b1);
                MMA16816(oacc[2 * dp + 1], pa[kt], b2, b3);
            }
        }
    }

    // ---- finalize: O / l, write fp32 out ----
    {
        float inv0 = 1.0f / l0, inv1 = 1.0f / l1;
        float* ob0 = out + (size_t)rr0 * QSTRIDE + (size_t)h * HD + ((lane & 3) << 1);
        float* ob1 = ob0 + 8 * QSTRIDE;
        #pragma unroll
        for (int nt = 0; nt < 16; ++nt) {
            float2 w0 = { oacc[nt][0] * inv0, oacc[nt][1] * inv0 };
            float2 w1 = { oacc[nt][2] * inv1, oacc[nt][3] * inv1 };
            *(float2*)(ob0 + nt * 8) = w0;
            *(float2*)(ob1 + nt * 8) = w1;
        }
    }
}

extern "C" void kernel_launch(void* const* d_in, const int* in_sizes, int n_in,
                              void* d_out, int out_size)
{
    const float* q = (const float*)d_in[0];
    const float* k = (const float*)d_in[1];
    const float* v = (const float*)d_in[2];
    float* out = (float*)d_out;

    cudaFuncSetAttribute(attn_hmma_kernel,
                         cudaFuncAttributeMaxDynamicSharedMemorySize, SMEM_BYTES);

    dim3 grid(SEQ / BM, NH);
    attn_hmma_kernel<<<grid, 128, SMEM_BYTES>>>(q, k, v, out);
}

// round 6
// speedup vs baseline: 1.1217x; 1.1217x over previous
#include <cuda_runtime.h>
#include <cuda_fp16.h>
#include <cstdint>

#define SEQ   2048
#define NH    32
#define NKV   8
#define HD    128
#define BM    128
#define BN    64
#define QSTRIDE  (NH*HD)
#define KVSTRIDE (NKV*HD)
#define QSCALE (0.08838834764831845f * 1.4426950408889634f)

#define SSTRIDE 136                       /* fp16 elems per smem row */
#define QS_OFF  0
#define TILE_B  (BN * SSTRIDE * 2)        /* 17408 */
#define KS_OFF(b) (BM * SSTRIDE * 2 + (b) * TILE_B)
#define VS_OFF(b) (BM * SSTRIDE * 2 + 2 * TILE_B + (b) * TILE_B)
#define SMEM_BYTES (BM * SSTRIDE * 2 + 4 * TILE_B)   /* 104448 */

__device__ __half d_qh[(size_t)SEQ * QSTRIDE];
__device__ __half d_kh[(size_t)SEQ * KVSTRIDE];
__device__ __half d_vh[(size_t)SEQ * KVSTRIDE];

__device__ __forceinline__ uint32_t smem_u32(const void* p) {
    uint32_t a;
    asm("{ .reg .u64 t; cvta.to.shared.u64 t, %1; cvt.u32.u64 %0, t; }" : "=r"(a) : "l"(p));
    return a;
}

#define LDSM_X4(r0,r1,r2,r3,a) \
    asm volatile("ldmatrix.sync.aligned.m8n8.x4.shared.b16 {%0,%1,%2,%3}, [%4];" \
                 : "=r"(r0),"=r"(r1),"=r"(r2),"=r"(r3) : "r"(a))
#define LDSM_X4T(r0,r1,r2,r3,a) \
    asm volatile("ldmatrix.sync.aligned.m8n8.x4.trans.shared.b16 {%0,%1,%2,%3}, [%4];" \
                 : "=r"(r0),"=r"(r1),"=r"(r2),"=r"(r3) : "r"(a))
#define LDSM_X2T(r0,r1,a) \
    asm volatile("ldmatrix.sync.aligned.m8n8.x2.trans.shared.b16 {%0,%1}, [%2];" \
                 : "=r"(r0),"=r"(r1) : "r"(a))

#define MMA16816(d, a, b0, b1) \
    asm volatile("mma.sync.aligned.m16n8k16.row.col.f32.f16.f16.f32 " \
                 "{%0,%1,%2,%3}, {%4,%5,%6,%7}, {%8,%9}, {%0,%1,%2,%3};" \
                 : "+f"((d)[0]),"+f"((d)[1]),"+f"((d)[2]),"+f"((d)[3]) \
                 : "r"((a)[0]),"r"((a)[1]),"r"((a)[2]),"r"((a)[3]),"r"(b0),"r"(b1))

#define CP_ASYNC16(dst, src) \
    asm volatile("cp.async.cg.shared.global [%0], [%1], 16;" :: "r"(dst), "l"(src) : "memory")
#define CP_COMMIT() asm volatile("cp.async.commit_group;" ::: "memory")
#define CP_WAIT0()  asm volatile("cp.async.wait_group 0;" ::: "memory")

__device__ __forceinline__ float ex2f(float x) {
    float r;
    asm("ex2.approx.ftz.f32 %0, %1;" : "=f"(r) : "f"(x));
    return r;
}
__device__ __forceinline__ uint32_t packh2(float a, float b) {
    __half2 h = __floats2half2_rn(a, b);
    return *(uint32_t*)&h;
}

// ---- preprocess: fp32 -> fp16 (Q scaled) into global scratch ----
__global__ void cvt_kernel(const float* __restrict__ q, const float* __restrict__ k,
                           const float* __restrict__ v)
{
    int idx = blockIdx.x * blockDim.x + threadIdx.x;   // float4 slot
    if (blockIdx.y == 0) {
        float4 val = ((const float4*)q)[idx];
        uint2 hh;
        hh.x = packh2(val.x * QSCALE, val.y * QSCALE);
        hh.y = packh2(val.z * QSCALE, val.w * QSCALE);
        *(uint2*)(d_qh + (size_t)idx * 4) = hh;
    } else if (idx < SEQ * KVSTRIDE / 4) {
        const float* src = (blockIdx.y == 1) ? k : v;
        __half* dst = (blockIdx.y == 1) ? d_kh : d_vh;
        float4 val = ((const float4*)src)[idx];
        uint2 hh;
        hh.x = packh2(val.x, val.y);
        hh.y = packh2(val.z, val.w);
        *(uint2*)(dst + (size_t)idx * 4) = hh;
    }
}

__global__ __launch_bounds__(256, 1)
void attn_hmma_kernel(float* __restrict__ out)
{
    extern __shared__ char smem[];
    const uint32_t sb = smem_u32(smem);
    const int tid  = threadIdx.x;
    const int wid  = tid >> 5;
    const int lane = tid & 31;
    const int qt   = 15 - (int)blockIdx.x;        // long CTAs first
    const int h    = (int)blockIdx.y;
    const int hk   = h >> 2;
    const int q0   = qt * BM;
    const int NT   = 2 * qt + 2;

    const __half* kg = d_kh + (size_t)hk * HD;
    const __half* vg = d_vh + (size_t)hk * HD;

    // ---- prologue: async-load KV tile 0 into buffer 0 ----
    {
        #pragma unroll
        for (int it = 0; it < 4; ++it) {
            int c = it * 256 + tid;                // 1024 16B-chunks per tile
            int row = c >> 4, col8 = (c & 15) * 8;
            uint32_t so = (uint32_t)(row * SSTRIDE + col8) * 2;
            CP_ASYNC16(sb + KS_OFF(0) + so, kg + (size_t)row * KVSTRIDE + col8);
            CP_ASYNC16(sb + VS_OFF(0) + so, vg + (size_t)row * KVSTRIDE + col8);
        }
        CP_COMMIT();
    }

    // ---- load Q tile (already fp16+scaled) into SMEM ----
    {
        const __half* qb = d_qh + (size_t)q0 * QSTRIDE + (size_t)h * HD;
        #pragma unroll
        for (int it = 0; it < 8; ++it) {
            int slot = it * 256 + tid;             // 2048 8-half chunks
            int r = slot >> 4, c8 = (slot & 15) * 8;
            uint4 val = *(const uint4*)(qb + (size_t)r * QSTRIDE + c8);
            *(uint4*)(smem + QS_OFF + (r * SSTRIDE + c8) * 2) = val;
        }
    }
    // ---- ones-column init for V buffers (col 128 = 1.0h, 129..135 = 0) ----
    if (tid < 64) {
        uint4 pad = make_uint4(0x00003C00u, 0u, 0u, 0u);
        *(uint4*)(smem + VS_OFF(0) + (tid * SSTRIDE + 128) * 2) = pad;
        *(uint4*)(smem + VS_OFF(1) + (tid * SSTRIDE + 128) * 2) = pad;
    }
    __syncthreads();

    // ---- Q A-fragments into registers (held for the whole kernel) ----
    uint32_t qa[8][4];
    {
        int row = wid * 16 + (lane & 15);
        #pragma unroll
        for (int ks = 0; ks < 8; ++ks) {
            uint32_t a = sb + QS_OFF + (row * SSTRIDE + ks * 16 + (lane >> 4) * 8) * 2;
            LDSM_X4(qa[ks][0], qa[ks][1], qa[ks][2], qa[ks][3], a);
        }
    }

    float oacc[16][4];
    #pragma unroll
    for (int i = 0; i < 16; ++i)
        #pragma unroll
        for (int j = 0; j < 4; ++j) oacc[i][j] = 0.f;
    float osum[4] = {0.f, 0.f, 0.f, 0.f};
    float m0 = -1e30f, m1 = -1e30f;

    const int rr0 = q0 + wid * 16 + (lane >> 2);

    for (int jt = 0; jt < NT; ++jt) {
        const int j0  = jt * BN;
        const int cur = jt & 1;

        CP_WAIT0();
        __syncthreads();

        // ---- async-load next KV tile into the other buffer ----
        if (jt + 1 < NT) {
            int j0n = j0 + BN;
            #pragma unroll
            for (int it = 0; it < 4; ++it) {
                int c = it * 256 + tid;
                int row = c >> 4, col8 = (c & 15) * 8;
                uint32_t so = (uint32_t)(row * SSTRIDE + col8) * 2;
                CP_ASYNC16(sb + KS_OFF(cur ^ 1) + so, kg + (size_t)(j0n + row) * KVSTRIDE + col8);
                CP_ASYNC16(sb + VS_OFF(cur ^ 1) + so, vg + (size_t)(j0n + row) * KVSTRIDE + col8);
            }
            CP_COMMIT();
        }

        // ---- S = Q @ K^T ----
        float sacc[8][4];
        #pragma unroll
        for (int i = 0; i < 8; ++i)
            #pragma unroll
            for (int j = 0; j < 4; ++j) sacc[i][j] = 0.f;

        #pragma unroll
        for (int nt = 0; nt < 8; ++nt) {
            uint32_t krow = sb + KS_OFF(cur) + ((nt * 8 + (lane & 7)) * SSTRIDE) * 2;
            #pragma unroll
            for (int kp = 0; kp < 4; ++kp) {
                uint32_t b0, b1, b2, b3;
                uint32_t a = krow + (kp * 32 + (lane >> 3) * 8) * 2;
                LDSM_X4(b0, b1, b2, b3, a);
                MMA16816(sacc[nt], qa[2 * kp],     b0, b1);
                MMA16816(sacc[nt], qa[2 * kp + 1], b2, b3);
            }
        }

        // ---- causal mask (last two tiles cover the diagonal) ----
        if (jt >= NT - 2) {
            #pragma unroll
            for (int nt = 0; nt < 8; ++nt) {
                int jc = j0 + nt * 8 + ((lane & 3) << 1);
                if (jc     > rr0    ) sacc[nt][0] = -1e30f;
                if (jc + 1 > rr0    ) sacc[nt][1] = -1e30f;
                if (jc     > rr0 + 8) sacc[nt][2] = -1e30f;
                if (jc + 1 > rr0 + 8) sacc[nt][3] = -1e30f;
            }
        }

        // ---- online softmax: max + exp (sum comes from the MMA ones-column) ----
        float mx0 = -1e30f, mx1 = -1e30f;
        #pragma unroll
        for (int nt = 0; nt < 8; ++nt) {
            mx0 = fmaxf(mx0, fmaxf(sacc[nt][0], sacc[nt][1]));
            mx1 = fmaxf(mx1, fmaxf(sacc[nt][2], sacc[nt][3]));
        }
        mx0 = fmaxf(mx0, __shfl_xor_sync(0xffffffffu, mx0, 1));
        mx0 = fmaxf(mx0, __shfl_xor_sync(0xffffffffu, mx0, 2));
        mx1 = fmaxf(mx1, __shfl_xor_sync(0xffffffffu, mx1, 1));
        mx1 = fmaxf(mx1, __shfl_xor_sync(0xffffffffu, mx1, 2));

        float mn0 = fmaxf(m0, mx0), mn1 = fmaxf(m1, mx1);
        float al0 = ex2f(m0 - mn0), al1 = ex2f(m1 - mn1);
        m0 = mn0; m1 = mn1;

        #pragma unroll
        for (int nt = 0; nt < 8; ++nt) {
            sacc[nt][0] = ex2f(sacc[nt][0] - mn0);
            sacc[nt][1] = ex2f(sacc[nt][1] - mn0);
            sacc[nt][2] = ex2f(sacc[nt][2] - mn1);
            sacc[nt][3] = ex2f(sacc[nt][3] - mn1);
        }

        // ---- pack P into A-fragments ----
        uint32_t pa[4][4];
        #pragma unroll
        for (int t = 0; t < 4; ++t) {
            pa[t][0] = packh2(sacc[2 * t][0],     sacc[2 * t][1]);
            pa[t][1] = packh2(sacc[2 * t][2],     sacc[2 * t][3]);
            pa[t][2] = packh2(sacc[2 * t + 1][0], sacc[2 * t + 1][1]);
            pa[t][3] = packh2(sacc[2 * t + 1][2], sacc[2 * t + 1][3]);
        }

        // ---- conditional rescale of O and row-sum accumulators ----
        if (__any_sync(0xffffffffu, (al0 < 1.0f) || (al1 < 1.0f))) {
            #pragma unroll
            for (int nt = 0; nt < 16; ++nt) {
                oacc[nt][0] *= al0; oacc[nt][1] *= al0;
                oacc[nt][2] *= al1; oacc[nt][3] *= al1;
            }
            osum[0] *= al0; osum[1] *= al0;
            osum[2] *= al1; osum[3] *= al1;
        }

        // ---- O += P @ V ; row-sum via ones-column ----
        #pragma unroll
        for (int dp = 0; dp < 8; ++dp) {
            #pragma unroll
            for (int kt = 0; kt < 4; ++kt) {
                uint32_t b0, b1, b2, b3;
                uint32_t a = sb + VS_OFF(cur) +
                    (((kt * 16) + (lane & 15)) * SSTRIDE + dp * 16 + (lane >> 4) * 8) * 2;
                LDSM_X4T(b0, b1, b2, b3, a);
                MMA16816(oacc[2 * dp],     pa[kt], b0, b1);
                MMA16816(oacc[2 * dp + 1], pa[kt], b2, b3);
            }
        }
        #pragma unroll
        for (int kt = 0; kt < 4; ++kt) {
            uint32_t b0, b1;
            uint32_t a = sb + VS_OFF(cur) + (((kt * 16) + (lane & 15)) * SSTRIDE + 128) * 2;
            LDSM_X2T(b0, b1, a);
            MMA16816(osum, pa[kt], b0, b1);
        }
    }

    // ---- finalize: l from ones-column (lane%4==0 holds it), divide, store ----
    {
        int qbase = lane & ~3;
        float l0 = __shfl_sync(0xffffffffu, osum[0], qbase);
        float l1 = __shfl_sync(0xffffffffu, osum[2], qbase);
        float inv0 = 1.0f / l0, inv1 = 1.0f / l1;
        float* ob0 = out + (size_t)rr0 * QSTRIDE + (size_t)h * HD + ((lane & 3) << 1);
        float* ob1 = ob0 + 8 * QSTRIDE;
        #pragma unroll
        for (int nt = 0; nt < 16; ++nt) {
            float2 w0 = { oacc[nt][0] * inv0, oacc[nt][1] * inv0 };
            float2 w1 = { oacc[nt][2] * inv1, oacc[nt][3] * inv1 };
            *(float2*)(ob0 + nt * 8) = w0;
            *(float2*)(ob1 + nt * 8) = w1;
        }
    }
}

extern "C" void kernel_launch(void* const* d_in, const int* in_sizes, int n_in,
                              void* d_out, int out_size)
{
    const float* q = (const float*)d_in[0];
    const float* k = (const float*)d_in[1];
    const float* v = (const float*)d_in[2];
    float* out = (float*)d_out;

    cudaFuncSetAttribute(attn_hmma_kernel,
                         cudaFuncAttributeMaxDynamicSharedMemorySize, SMEM_BYTES);

    dim3 cgrid(SEQ * QSTRIDE / 4 / 256, 3);
    cvt_kernel<<<cgrid, 256>>>(q, k, v);

    dim3 grid(SEQ / BM, NH);
    attn_hmma_kernel<<<grid, 256, SMEM_BYTES>>>(out);
}

// round 7
// speedup vs baseline: 1.2957x; 1.1551x over previous
#include <cuda_runtime.h>
#include <cuda_fp16.h>
#include <cstdint>

#define SEQ   2048
#define NH    32
#define NKV   8
#define HD    128
#define BM    64
#define BN    64
#define QSTRIDE  (NH*HD)
#define KVSTRIDE (NKV*HD)
#define QSCALE (0.08838834764831845f * 1.4426950408889634f)

#define SSTRIDE 136                       /* fp16 elems per smem row */
#define QS_OFF  0
#define TILE_B  (BN * SSTRIDE * 2)        /* 17408 */
#define KS_OFF(b) (BM * SSTRIDE * 2 + (b) * TILE_B)
#define VS_OFF(b) (BM * SSTRIDE * 2 + 2 * TILE_B + (b) * TILE_B)
#define SMEM_BYTES (BM * SSTRIDE * 2 + 4 * TILE_B)   /* 87040 */

__device__ __half d_qh[(size_t)SEQ * QSTRIDE];
__device__ __half d_kh[(size_t)SEQ * KVSTRIDE];
__device__ __half d_vh[(size_t)SEQ * KVSTRIDE];

__device__ __forceinline__ uint32_t smem_u32(const void* p) {
    uint32_t a;
    asm("{ .reg .u64 t; cvta.to.shared.u64 t, %1; cvt.u32.u64 %0, t; }" : "=r"(a) : "l"(p));
    return a;
}

#define LDSM_X4(r0,r1,r2,r3,a) \
    asm volatile("ldmatrix.sync.aligned.m8n8.x4.shared.b16 {%0,%1,%2,%3}, [%4];" \
                 : "=r"(r0),"=r"(r1),"=r"(r2),"=r"(r3) : "r"(a))
#define LDSM_X4T(r0,r1,r2,r3,a) \
    asm volatile("ldmatrix.sync.aligned.m8n8.x4.trans.shared.b16 {%0,%1,%2,%3}, [%4];" \
                 : "=r"(r0),"=r"(r1),"=r"(r2),"=r"(r3) : "r"(a))
#define LDSM_X2T(r0,r1,a) \
    asm volatile("ldmatrix.sync.aligned.m8n8.x2.trans.shared.b16 {%0,%1}, [%2];" \
                 : "=r"(r0),"=r"(r1) : "r"(a))

#define MMA16816(d, a, b0, b1) \
    asm volatile("mma.sync.aligned.m16n8k16.row.col.f32.f16.f16.f32 " \
                 "{%0,%1,%2,%3}, {%4,%5,%6,%7}, {%8,%9}, {%0,%1,%2,%3};" \
                 : "+f"((d)[0]),"+f"((d)[1]),"+f"((d)[2]),"+f"((d)[3]) \
                 : "r"((a)[0]),"r"((a)[1]),"r"((a)[2]),"r"((a)[3]),"r"(b0),"r"(b1))

#define CP_ASYNC16(dst, src) \
    asm volatile("cp.async.cg.shared.global [%0], [%1], 16;" :: "r"(dst), "l"(src) : "memory")
#define CP_COMMIT() asm volatile("cp.async.commit_group;" ::: "memory")
#define CP_WAIT0()  asm volatile("cp.async.wait_group 0;" ::: "memory")

__device__ __forceinline__ float ex2f(float x) {
    float r;
    asm("ex2.approx.ftz.f32 %0, %1;" : "=f"(r) : "f"(x));
    return r;
}
__device__ __forceinline__ uint32_t packh2(float a, float b) {
    __half2 h = __floats2half2_rn(a, b);
    return *(uint32_t*)&h;
}

// ---- preprocess: fp32 -> fp16 (Q scaled) into global scratch ----
__global__ void cvt_kernel(const float* __restrict__ q, const float* __restrict__ k,
                           const float* __restrict__ v)
{
    int idx = blockIdx.x * blockDim.x + threadIdx.x;   // float4 slot
    if (blockIdx.y == 0) {
        float4 val = ((const float4*)q)[idx];
        uint2 hh;
        hh.x = packh2(val.x * QSCALE, val.y * QSCALE);
        hh.y = packh2(val.z * QSCALE, val.w * QSCALE);
        *(uint2*)(d_qh + (size_t)idx * 4) = hh;
    } else if (idx < SEQ * KVSTRIDE / 4) {
        const float* src = (blockIdx.y == 1) ? k : v;
        __half* dst = (blockIdx.y == 1) ? d_kh : d_vh;
        float4 val = ((const float4*)src)[idx];
        uint2 hh;
        hh.x = packh2(val.x, val.y);
        hh.y = packh2(val.z, val.w);
        *(uint2*)(dst + (size_t)idx * 4) = hh;
    }
}

__global__ __launch_bounds__(128, 2)
void attn_hmma_kernel(float* __restrict__ out)
{
    extern __shared__ char smem[];
    const uint32_t sb = smem_u32(smem);
    const int tid  = threadIdx.x;
    const int wid  = tid >> 5;
    const int lane = tid & 31;
    const int qt   = 31 - (int)blockIdx.x;        // long CTAs first
    const int h    = (int)blockIdx.y;
    const int hk   = h >> 2;
    const int q0   = qt * BM;
    const int NT   = qt + 1;

    const __half* kg = d_kh + (size_t)hk * HD;
    const __half* vg = d_vh + (size_t)hk * HD;

    // ---- prologue: async-load KV tile 0 into buffer 0 ----
    {
        #pragma unroll
        for (int it = 0; it < 8; ++it) {
            int c = it * 128 + tid;                // 1024 16B-chunks per tile
            int row = c >> 4, col8 = (c & 15) * 8;
            uint32_t so = (uint32_t)(row * SSTRIDE + col8) * 2;
            CP_ASYNC16(sb + KS_OFF(0) + so, kg + (size_t)row * KVSTRIDE + col8);
            CP_ASYNC16(sb + VS_OFF(0) + so, vg + (size_t)row * KVSTRIDE + col8);
        }
        CP_COMMIT();
    }

    // ---- load Q tile (already fp16+scaled) into SMEM ----
    {
        const __half* qb = d_qh + (size_t)q0 * QSTRIDE + (size_t)h * HD;
        #pragma unroll
        for (int it = 0; it < 8; ++it) {
            int slot = it * 128 + tid;             // 1024 8-half chunks
            int r = slot >> 4, c8 = (slot & 15) * 8;
            uint4 val = *(const uint4*)(qb + (size_t)r * QSTRIDE + c8);
            *(uint4*)(smem + QS_OFF + (r * SSTRIDE + c8) * 2) = val;
        }
    }
    // ---- ones-column init for V buffers (col 128 = 1.0h, 129..135 = 0) ----
    if (tid < 64) {
        uint4 pad = make_uint4(0x00003C00u, 0u, 0u, 0u);
        *(uint4*)(smem + VS_OFF(0) + (tid * SSTRIDE + 128) * 2) = pad;
        *(uint4*)(smem + VS_OFF(1) + (tid * SSTRIDE + 128) * 2) = pad;
    }
    __syncthreads();

    // ---- Q A-fragments into registers (held for the whole kernel) ----
    uint32_t qa[8][4];
    {
        int row = wid * 16 + (lane & 15);
        #pragma unroll
        for (int ks = 0; ks < 8; ++ks) {
            uint32_t a = sb + QS_OFF + (row * SSTRIDE + ks * 16 + (lane >> 4) * 8) * 2;
            LDSM_X4(qa[ks][0], qa[ks][1], qa[ks][2], qa[ks][3], a);
        }
    }

    float oacc[16][4];
    #pragma unroll
    for (int i = 0; i < 16; ++i)
        #pragma unroll
        for (int j = 0; j < 4; ++j) oacc[i][j] = 0.f;
    float osum[4] = {0.f, 0.f, 0.f, 0.f};
    float m0 = -1e30f, m1 = -1e30f;

    const int rr0 = q0 + wid * 16 + (lane >> 2);

    for (int jt = 0; jt < NT; ++jt) {
        const int j0  = jt * BN;
        const int cur = jt & 1;

        CP_WAIT0();
        __syncthreads();

        // ---- async-load next KV tile into the other buffer ----
        if (jt + 1 < NT) {
            int j0n = j0 + BN;
            #pragma unroll
            for (int it = 0; it < 8; ++it) {
                int c = it * 128 + tid;
                int row = c >> 4, col8 = (c & 15) * 8;
                uint32_t so = (uint32_t)(row * SSTRIDE + col8) * 2;
                CP_ASYNC16(sb + KS_OFF(cur ^ 1) + so, kg + (size_t)(j0n + row) * KVSTRIDE + col8);
                CP_ASYNC16(sb + VS_OFF(cur ^ 1) + so, vg + (size_t)(j0n + row) * KVSTRIDE + col8);
            }
            CP_COMMIT();
        }

        // ---- S = Q @ K^T ----
        float sacc[8][4];
        #pragma unroll
        for (int i = 0; i < 8; ++i)
            #pragma unroll
            for (int j = 0; j < 4; ++j) sacc[i][j] = 0.f;

        #pragma unroll
        for (int nt = 0; nt < 8; ++nt) {
            uint32_t krow = sb + KS_OFF(cur) + ((nt * 8 + (lane & 7)) * SSTRIDE) * 2;
            #pragma unroll
            for (int kp = 0; kp < 4; ++kp) {
                uint32_t b0, b1, b2, b3;
                uint32_t a = krow + (kp * 32 + (lane >> 3) * 8) * 2;
                LDSM_X4(b0, b1, b2, b3, a);
                MMA16816(sacc[nt], qa[2 * kp],     b0, b1);
                MMA16816(sacc[nt], qa[2 * kp + 1], b2, b3);
            }
        }

        // ---- causal mask (diagonal tile only) ----
        if (jt == NT - 1) {
            #pragma unroll
            for (int nt = 0; nt < 8; ++nt) {
                int jc = j0 + nt * 8 + ((lane & 3) << 1);
                if (jc     > rr0    ) sacc[nt][0] = -1e30f;
                if (jc + 1 > rr0    ) sacc[nt][1] = -1e30f;
                if (jc     > rr0 + 8) sacc[nt][2] = -1e30f;
                if (jc + 1 > rr0 + 8) sacc[nt][3] = -1e30f;
            }
        }

        // ---- online softmax: max + exp (sum comes from the MMA ones-column) ----
        float mx0 = -1e30f, mx1 = -1e30f;
        #pragma unroll
        for (int nt = 0; nt < 8; ++nt) {
            mx0 = fmaxf(mx0, fmaxf(sacc[nt][0], sacc[nt][1]));
            mx1 = fmaxf(mx1, fmaxf(sacc[nt][2], sacc[nt][3]));
        }
        mx0 = fmaxf(mx0, __shfl_xor_sync(0xffffffffu, mx0, 1));
        mx0 = fmaxf(mx0, __shfl_xor_sync(0xffffffffu, mx0, 2));
        mx1 = fmaxf(mx1, __shfl_xor_sync(0xffffffffu, mx1, 1));
        mx1 = fmaxf(mx1, __shfl_xor_sync(0xffffffffu, mx1, 2));

        float mn0 = fmaxf(m0, mx0), mn1 = fmaxf(m1, mx1);
        float al0 = ex2f(m0 - mn0), al1 = ex2f(m1 - mn1);
        m0 = mn0; m1 = mn1;

        #pragma unroll
        for (int nt = 0; nt < 8; ++nt) {
            sacc[nt][0] = ex2f(sacc[nt][0] - mn0);
            sacc[nt][1] = ex2f(sacc[nt][1] - mn0);
            sacc[nt][2] = ex2f(sacc[nt][2] - mn1);
            sacc[nt][3] = ex2f(sacc[nt][3] - mn1);
        }

        // ---- pack P into A-fragments ----
        uint32_t pa[4][4];
        #pragma unroll
        for (int t = 0; t < 4; ++t) {
            pa[t][0] = packh2(sacc[2 * t][0],     sacc[2 * t][1]);
            pa[t][1] = packh2(sacc[2 * t][2],     sacc[2 * t][3]);
            pa[t][2] = packh2(sacc[2 * t + 1][0], sacc[2 * t + 1][1]);
            pa[t][3] = packh2(sacc[2 * t + 1][2], sacc[2 * t + 1][3]);
        }

        // ---- conditional rescale of O and row-sum accumulators ----
        if (__any_sync(0xffffffffu, (al0 < 1.0f) || (al1 < 1.0f))) {
            #pragma unroll
            for (int nt = 0; nt < 16; ++nt) {
                oacc[nt][0] *= al0; oacc[nt][1] *= al0;
                oacc[nt][2] *= al1; oacc[nt][3] *= al1;
            }
            osum[0] *= al0; osum[1] *= al0;
            osum[2] *= al1; osum[3] *= al1;
        }

        // ---- O += P @ V ; row-sum via ones-column ----
        #pragma unroll
        for (int dp = 0; dp < 8; ++dp) {
            #pragma unroll
            for (int kt = 0; kt < 4; ++kt) {
                uint32_t b0, b1, b2, b3;
                uint32_t a = sb + VS_OFF(cur) +
                    (((kt * 16) + (lane & 15)) * SSTRIDE + dp * 16 + (lane >> 4) * 8) * 2;
                LDSM_X4T(b0, b1, b2, b3, a);
                MMA16816(oacc[2 * dp],     pa[kt], b0, b1);
                MMA16816(oacc[2 * dp + 1], pa[kt], b2, b3);
            }
        }
        #pragma unroll
        for (int kt = 0; kt < 4; ++kt) {
            uint32_t b0, b1;
            uint32_t a = sb + VS_OFF(cur) + (((kt * 16) + (lane & 15)) * SSTRIDE + 128) * 2;
            LDSM_X2T(b0, b1, a);
            MMA16816(osum, pa[kt], b0, b1);
        }
    }

    // ---- finalize: l from ones-column (lane%4==0 holds it), divide, store ----
    {
        int qbase = lane & ~3;
        float l0 = __shfl_sync(0xffffffffu, osum[0], qbase);
        float l1 = __shfl_sync(0xffffffffu, osum[2], qbase);
        float inv0 = 1.0f / l0, inv1 = 1.0f / l1;
        float* ob0 = out + (size_t)rr0 * QSTRIDE + (size_t)h * HD + ((lane & 3) << 1);
        float* ob1 = ob0 + 8 * QSTRIDE;
        #pragma unroll
        for (int nt = 0; nt < 16; ++nt) {
            float2 w0 = { oacc[nt][0] * inv0, oacc[nt][1] * inv0 };
            float2 w1 = { oacc[nt][2] * inv1, oacc[nt][3] * inv1 };
            *(float2*)(ob0 + nt * 8) = w0;
            *(float2*)(ob1 + nt * 8) = w1;
        }
    }
}

extern "C" void kernel_launch(void* const* d_in, const int* in_sizes, int n_in,
                              void* d_out, int out_size)
{
    const float* q = (const float*)d_in[0];
    const float* k = (const float*)d_in[1];
    const float* v = (const float*)d_in[2];
    float* out = (float*)d_out;

    cudaFuncSetAttribute(attn_hmma_kernel,
                         cudaFuncAttributeMaxDynamicSharedMemorySize, SMEM_BYTES);

    dim3 cgrid(SEQ * QSTRIDE / 4 / 256, 3);
    cvt_kernel<<<cgrid, 256>>>(q, k, v);

    dim3 grid(SEQ / BM, NH);
    attn_hmma_kernel<<<grid, 128, SMEM_BYTES>>>(out);
}

// round 8
// speedup vs baseline: 1.4310x; 1.1044x over previous
#include <cuda_runtime.h>
#include <cuda_fp16.h>
#include <cstdint>

#define SEQ   2048
#define NH    32
#define NKV   8
#define HD    128
#define BM    64
#define BN    64
#define QSTRIDE  (NH*HD)
#define KVSTRIDE (NKV*HD)
#define QSCALE (0.08838834764831845f * 1.4426950408889634f)

#define SSTRIDE 136                       /* fp16 elems per smem row */
#define QS_OFF  0
#define TILE_B  (BN * SSTRIDE * 2)        /* 17408 */
#define KS_OFF(b) (BM * SSTRIDE * 2 + (b) * TILE_B)
#define VS_OFF(b) (BM * SSTRIDE * 2 + 2 * TILE_B + (b) * TILE_B)
#define SMEM_BYTES (BM * SSTRIDE * 2 + 4 * TILE_B)   /* 87040 */

__device__ __half d_kh[(size_t)SEQ * KVSTRIDE];
__device__ __half d_vh[(size_t)SEQ * KVSTRIDE];

__device__ __forceinline__ uint32_t smem_u32(const void* p) {
    uint32_t a;
    asm("{ .reg .u64 t; cvta.to.shared.u64 t, %1; cvt.u32.u64 %0, t; }" : "=r"(a) : "l"(p));
    return a;
}

#define LDSM_X4(r0,r1,r2,r3,a) \
    asm volatile("ldmatrix.sync.aligned.m8n8.x4.shared.b16 {%0,%1,%2,%3}, [%4];" \
                 : "=r"(r0),"=r"(r1),"=r"(r2),"=r"(r3) : "r"(a))
#define LDSM_X4T(r0,r1,r2,r3,a) \
    asm volatile("ldmatrix.sync.aligned.m8n8.x4.trans.shared.b16 {%0,%1,%2,%3}, [%4];" \
                 : "=r"(r0),"=r"(r1),"=r"(r2),"=r"(r3) : "r"(a))
#define LDSM_X2T(r0,r1,a) \
    asm volatile("ldmatrix.sync.aligned.m8n8.x2.trans.shared.b16 {%0,%1}, [%2];" \
                 : "=r"(r0),"=r"(r1) : "r"(a))

#define MMA16816(d, a, b0, b1) \
    asm volatile("mma.sync.aligned.m16n8k16.row.col.f32.f16.f16.f32 " \
                 "{%0,%1,%2,%3}, {%4,%5,%6,%7}, {%8,%9}, {%0,%1,%2,%3};" \
                 : "+f"((d)[0]),"+f"((d)[1]),"+f"((d)[2]),"+f"((d)[3]) \
                 : "r"((a)[0]),"r"((a)[1]),"r"((a)[2]),"r"((a)[3]),"r"(b0),"r"(b1))

#define CP_ASYNC16(dst, src) \
    asm volatile("cp.async.cg.shared.global [%0], [%1], 16;" :: "r"(dst), "l"(src) : "memory")
#define CP_COMMIT() asm volatile("cp.async.commit_group;" ::: "memory")
#define CP_WAIT0()  asm volatile("cp.async.wait_group 0;" ::: "memory")

__device__ __forceinline__ float ex2f(float x) {
    float r;
    asm("ex2.approx.ftz.f32 %0, %1;" : "=f"(r) : "f"(x));
    return r;
}
__device__ __forceinline__ uint32_t packh2(float a, float b) {
    __half2 h = __floats2half2_rn(a, b);
    return *(uint32_t*)&h;
}
// pack {lo,hi} to f16x2 and exponentiate both halves in one MUFU op
__device__ __forceinline__ uint32_t exp2h2(float lo, float hi) {
    uint32_t r;
    asm("{ .reg .b32 t; cvt.rn.satfinite.f16x2.f32 t, %1, %2;\n\t"
        "ex2.approx.f16x2 %0, t; }"
        : "=r"(r) : "f"(hi), "f"(lo));
    return r;
}

// ---- preprocess: K/V fp32 -> fp16 into global scratch ----
__global__ void cvt_kernel(const float* __restrict__ k, const float* __restrict__ v)
{
    int idx = blockIdx.x * blockDim.x + threadIdx.x;   // float4 slot
    if (idx < SEQ * KVSTRIDE / 4) {
        const float* src = (blockIdx.y == 0) ? k : v;
        __half* dst = (blockIdx.y == 0) ? d_kh : d_vh;
        float4 val = ((const float4*)src)[idx];
        uint2 hh;
        hh.x = packh2(val.x, val.y);
        hh.y = packh2(val.z, val.w);
        *(uint2*)(dst + (size_t)idx * 4) = hh;
    }
}

__global__ __launch_bounds__(128, 2)
void attn_hmma_kernel(const float* __restrict__ q, float* __restrict__ out)
{
    extern __shared__ char smem[];
    const uint32_t sb = smem_u32(smem);
    const int tid  = threadIdx.x;
    const int wid  = tid >> 5;
    const int lane = tid & 31;
    const int qt   = 31 - (int)blockIdx.x;        // long CTAs first
    const int h    = (int)blockIdx.y;
    const int hk   = h >> 2;
    const int q0   = qt * BM;
    const int NT   = qt + 1;

    const __half* kg = d_kh + (size_t)hk * HD;
    const __half* vg = d_vh + (size_t)hk * HD;

    // ---- prologue: async-load KV tile 0 into buffer 0 ----
    {
        #pragma unroll
        for (int it = 0; it < 8; ++it) {
            int c = it * 128 + tid;                // 1024 16B-chunks per tile
            int row = c >> 4, col8 = (c & 15) * 8;
            uint32_t so = (uint32_t)(row * SSTRIDE + col8) * 2;
            CP_ASYNC16(sb + KS_OFF(0) + so, kg + (size_t)row * KVSTRIDE + col8);
            CP_ASYNC16(sb + VS_OFF(0) + so, vg + (size_t)row * KVSTRIDE + col8);
        }
        CP_COMMIT();
    }

    // ---- load + scale + convert Q tile (fp32 -> fp16 smem) ----
    {
        const float* qb = q + (size_t)q0 * QSTRIDE + (size_t)h * HD;
        #pragma unroll
        for (int it = 0; it < 16; ++it) {
            int slot = it * 128 + tid;             // 2048 float4 slots
            int r = slot >> 5, c4 = (slot & 31) << 2;
            float4 val = *(const float4*)(qb + (size_t)r * QSTRIDE + c4);
            uint2 hh;
            hh.x = packh2(val.x * QSCALE, val.y * QSCALE);
            hh.y = packh2(val.z * QSCALE, val.w * QSCALE);
            *(uint2*)(smem + QS_OFF + (r * SSTRIDE + c4) * 2) = hh;
        }
    }
    // ---- ones-column init for V buffers (col 128 = 1.0h, 129..135 = 0) ----
    if (tid < 64) {
        uint4 pad = make_uint4(0x00003C00u, 0u, 0u, 0u);
        *(uint4*)(smem + VS_OFF(0) + (tid * SSTRIDE + 128) * 2) = pad;
        *(uint4*)(smem + VS_OFF(1) + (tid * SSTRIDE + 128) * 2) = pad;
    }
    __syncthreads();

    // ---- Q A-fragments into registers (held for the whole kernel) ----
    uint32_t qa[8][4];
    {
        int row = wid * 16 + (lane & 15);
        #pragma unroll
        for (int ks = 0; ks < 8; ++ks) {
            uint32_t a = sb + QS_OFF + (row * SSTRIDE + ks * 16 + (lane >> 4) * 8) * 2;
            LDSM_X4(qa[ks][0], qa[ks][1], qa[ks][2], qa[ks][3], a);
        }
    }

    float oacc[16][4];
    #pragma unroll
    for (int i = 0; i < 16; ++i)
        #pragma unroll
        for (int j = 0; j < 4; ++j) oacc[i][j] = 0.f;
    float osum[4] = {0.f, 0.f, 0.f, 0.f};
    float m0 = -1e30f, m1 = -1e30f;

    const int rr0 = q0 + wid * 16 + (lane >> 2);

    for (int jt = 0; jt < NT; ++jt) {
        const int j0  = jt * BN;
        const int cur = jt & 1;

        CP_WAIT0();
        __syncthreads();

        // ---- async-load next KV tile into the other buffer ----
        if (jt + 1 < NT) {
            int j0n = j0 + BN;
            #pragma unroll
            for (int it = 0; it < 8; ++it) {
                int c = it * 128 + tid;
                int row = c >> 4, col8 = (c & 15) * 8;
                uint32_t so = (uint32_t)(row * SSTRIDE + col8) * 2;
                CP_ASYNC16(sb + KS_OFF(cur ^ 1) + so, kg + (size_t)(j0n + row) * KVSTRIDE + col8);
                CP_ASYNC16(sb + VS_OFF(cur ^ 1) + so, vg + (size_t)(j0n + row) * KVSTRIDE + col8);
            }
            CP_COMMIT();
        }

        // ---- S = Q @ K^T ----
        float sacc[8][4];
        #pragma unroll
        for (int i = 0; i < 8; ++i)
            #pragma unroll
            for (int j = 0; j < 4; ++j) sacc[i][j] = 0.f;

        #pragma unroll
        for (int nt = 0; nt < 8; ++nt) {
            uint32_t krow = sb + KS_OFF(cur) + ((nt * 8 + (lane & 7)) * SSTRIDE) * 2;
            #pragma unroll
            for (int kp = 0; kp < 4; ++kp) {
                uint32_t b0, b1, b2, b3;
                uint32_t a = krow + (kp * 32 + (lane >> 3) * 8) * 2;
                LDSM_X4(b0, b1, b2, b3, a);
                MMA16816(sacc[nt], qa[2 * kp],     b0, b1);
                MMA16816(sacc[nt], qa[2 * kp + 1], b2, b3);
            }
        }

        // ---- causal mask (diagonal tile only) ----
        if (jt == NT - 1) {
            #pragma unroll
            for (int nt = 0; nt < 8; ++nt) {
                int jc = j0 + nt * 8 + ((lane & 3) << 1);
                if (jc     > rr0    ) sacc[nt][0] = -1e30f;
                if (jc + 1 > rr0    ) sacc[nt][1] = -1e30f;
                if (jc     > rr0 + 8) sacc[nt][2] = -1e30f;
                if (jc + 1 > rr0 + 8) sacc[nt][3] = -1e30f;
            }
        }

        // ---- online softmax: max (sum comes from the MMA ones-column) ----
        float mx0 = -1e30f, mx1 = -1e30f;
        #pragma unroll
        for (int nt = 0; nt < 8; ++nt) {
            mx0 = fmaxf(mx0, fmaxf(sacc[nt][0], sacc[nt][1]));
            mx1 = fmaxf(mx1, fmaxf(sacc[nt][2], sacc[nt][3]));
        }
        mx0 = fmaxf(mx0, __shfl_xor_sync(0xffffffffu, mx0, 1));
        mx0 = fmaxf(mx0, __shfl_xor_sync(0xffffffffu, mx0, 2));
        mx1 = fmaxf(mx1, __shfl_xor_sync(0xffffffffu, mx1, 1));
        mx1 = fmaxf(mx1, __shfl_xor_sync(0xffffffffu, mx1, 2));

        float mn0 = fmaxf(m0, mx0), mn1 = fmaxf(m1, mx1);
        float al0 = ex2f(m0 - mn0), al1 = ex2f(m1 - mn1);
        m0 = mn0; m1 = mn1;

        // ---- exp pairwise in fp16: directly produces P A-fragments ----
        uint32_t pa[4][4];
        #pragma unroll
        for (int t = 0; t < 4; ++t) {
            pa[t][0] = exp2h2(sacc[2 * t][0]     - mn0, sacc[2 * t][1]     - mn0);
            pa[t][1] = exp2h2(sacc[2 * t][2]     - mn1, sacc[2 * t][3]     - mn1);
            pa[t][2] = exp2h2(sacc[2 * t + 1][0] - mn0, sacc[2 * t + 1][1] - mn0);
            pa[t][3] = exp2h2(sacc[2 * t + 1][2] - mn1, sacc[2 * t + 1][3] - mn1);
        }

        // ---- conditional rescale of O and row-sum accumulators ----
        if (__any_sync(0xffffffffu, (al0 < 1.0f) || (al1 < 1.0f))) {
            #pragma unroll
            for (int nt = 0; nt < 16; ++nt) {
                oacc[nt][0] *= al0; oacc[nt][1] *= al0;
                oacc[nt][2] *= al1; oacc[nt][3] *= al1;
            }
            osum[0] *= al0; osum[1] *= al0;
            osum[2] *= al1; osum[3] *= al1;
        }

        // ---- O += P @ V ; row-sum via ones-column ----
        #pragma unroll
        for (int dp = 0; dp < 8; ++dp) {
            #pragma unroll
            for (int kt = 0; kt < 4; ++kt) {
                uint32_t b0, b1, b2, b3;
                uint32_t a = sb + VS_OFF(cur) +
                    (((kt * 16) + (lane & 15)) * SSTRIDE + dp * 16 + (lane >> 4) * 8) * 2;
                LDSM_X4T(b0, b1, b2, b3, a);
                MMA16816(oacc[2 * dp],     pa[kt], b0, b1);
                MMA16816(oacc[2 * dp + 1], pa[kt], b2, b3);
            }
        }
        #pragma unroll
        for (int kt = 0; kt < 4; ++kt) {
            uint32_t b0, b1;
            uint32_t a = sb + VS_OFF(cur) + (((kt * 16) + (lane & 15)) * SSTRIDE + 128) * 2;
            LDSM_X2T(b0, b1, a);
            MMA16816(osum, pa[kt], b0, b1);
        }
    }

    // ---- finalize: l from ones-column (lane%4==0 holds it), divide, store ----
    {
        int qbase = lane & ~3;
        float l0 = __shfl_sync(0xffffffffu, osum[0], qbase);
        float l1 = __shfl_sync(0xffffffffu, osum[2], qbase);
        float inv0 = 1.0f / l0, inv1 = 1.0f / l1;
        float* ob0 = out + (size_t)rr0 * QSTRIDE + (size_t)h * HD + ((lane & 3) << 1);
        float* ob1 = ob0 + 8 * QSTRIDE;
        #pragma unroll
        for (int nt = 0; nt < 16; ++nt) {
            float2 w0 = { oacc[nt][0] * inv0, oacc[nt][1] * inv0 };
            float2 w1 = { oacc[nt][2] * inv1, oacc[nt][3] * inv1 };
            *(float2*)(ob0 + nt * 8) = w0;
            *(float2*)(ob1 + nt * 8) = w1;
        }
    }
}

extern "C" void kernel_launch(void* const* d_in, const int* in_sizes, int n_in,
                              void* d_out, int out_size)
{
    const float* q = (const float*)d_in[0];
    const float* k = (const float*)d_in[1];
    const float* v = (const float*)d_in[2];
    float* out = (float*)d_out;

    cudaFuncSetAttribute(attn_hmma_kernel,
                         cudaFuncAttributeMaxDynamicSharedMemorySize, SMEM_BYTES);

    dim3 cgrid(SEQ * KVSTRIDE / 4 / 256, 2);
    cvt_kernel<<<cgrid, 256>>>(k, v);

    dim3 grid(SEQ / BM, NH);
    attn_hmma_kernel<<<grid, 128, SMEM_BYTES>>>(q, out);
}